// round 8
// baseline (speedup 1.0000x reference)
#include <cuda_runtime.h>
#include <cstdint>

// OctonionLinear as dense tf32 mma.sync GEMM (portable sm_103 target):
//   Y[b, n] = sum_kk X[b, kk] * Bop(n, kk) + bias[n]
//   Bop(n=8i+c, kk) = W[i*32768 + kk*8 + c]
// M=512, N=4096, K=4096.
// R8: manual LDG->cvt->STS pipeline (cvt ONCE per element, outside mainloop),
// ldmatrix.x4 for both A and B fragments (B stored n-major, padded).
// Mainloop: 24 ldmatrix + 64 mma per warp per kt, zero CVT.

#define M_DIM 512
#define N_DIM 4096
#define K_DIM 4096
#define BM 128
#define BN 128
#define BK 32
#define NK (K_DIM / BK)            // 128
#define THREADS 256

#define A_STRIDE 36                               // padded floats per A row
#define A_STAGE_FLT (BM * A_STRIDE)               // 4608
#define B_OCT_FLT (8 * A_STRIDE)                  // 288 ([c=8][k=32 +pad4])
#define B_STAGE_FLT ((BN / 8) * B_OCT_FLT)        // 4608
#define SMEM_BYTES (2 * (A_STAGE_FLT + B_STAGE_FLT) * 4)  // 73728

__device__ __forceinline__ uint32_t smem_u32(const void* p) {
    uint32_t a;
    asm("{ .reg .u64 t; cvta.to.shared.u64 t, %1; cvt.u32.u64 %0, t; }" : "=r"(a) : "l"(p));
    return a;
}
__device__ __forceinline__ uint32_t f2tf(float f) {
    uint32_t r;
    asm("cvt.rna.tf32.f32 %0, %1;" : "=r"(r) : "f"(f));
    return r;
}
__device__ __forceinline__ void ldm4(uint32_t* r, uint32_t addr) {
    asm volatile("ldmatrix.sync.aligned.m8n8.x4.shared.b16 {%0,%1,%2,%3}, [%4];"
                 : "=r"(r[0]), "=r"(r[1]), "=r"(r[2]), "=r"(r[3]) : "r"(addr));
}
__device__ __forceinline__ void mma8(float* c, const uint32_t* a, const uint32_t* b) {
    asm volatile(
        "mma.sync.aligned.m16n8k8.row.col.f32.tf32.tf32.f32 "
        "{%0,%1,%2,%3}, {%4,%5,%6,%7}, {%8,%9}, {%0,%1,%2,%3};"
        : "+f"(c[0]), "+f"(c[1]), "+f"(c[2]), "+f"(c[3])
        : "r"(a[0]), "r"(a[1]), "r"(a[2]), "r"(a[3]), "r"(b[0]), "r"(b[1]));
}

__global__ __launch_bounds__(THREADS)
void oct_mma_tf32_ldm(const float* __restrict__ X,
                      const float* __restrict__ W,
                      const float* __restrict__ Bias,
                      float* __restrict__ Y)
{
    extern __shared__ float smem[];   // [2][A_STAGE][B? ] : A0,A1,B0,B1
    float* Asm = smem;                           // 2 stages of 4608
    float* Bsm = smem + 2 * A_STAGE_FLT;         // 2 stages of 4608
    const uint32_t sAu = smem_u32(Asm);
    const uint32_t sBu = smem_u32(Bsm);

    const int t = threadIdx.x;
    const int w = t >> 5;
    const int l = t & 31;
    const int bm = blockIdx.y * BM;
    const int bn = blockIdx.x * BN;
    const int wm = (w & 3) * 32;          // warp M base
    const int wn = (w >> 2) * 64;         // warp N base
    const int wnOct = wn >> 3;            // 0 or 8

    const int lr = l >> 2;
    const int lc = l & 3;
    const int i0 = bn >> 3;

    // ---- LDG/STS mappings (per thread: 4 A granules + 4 B granules of 16B) ----
    const int arow0 = t >> 3;             // +32 per r
    const int ac16  = t & 7;              // float4 index within A row
    const int boct0 = t >> 6;             // +4 per r
    const int binn  = t & 63;
    const int bkk   = binn >> 1;          // k within tile (0..31)
    const int bc0   = (binn & 1) * 4;     // starting c of granule

    float4 pa[4], pb[4];

    auto ldg_stage = [&](int kt) {
        #pragma unroll
        for (int r = 0; r < 4; r++)
            pa[r] = *(const float4*)(X + (size_t)(bm + arow0 + r * 32) * K_DIM
                                       + (size_t)kt * BK + ac16 * 4);
        #pragma unroll
        for (int r = 0; r < 4; r++)
            pb[r] = *(const float4*)(W + (size_t)(i0 + boct0 + r * 4) * 32768
                                       + (size_t)kt * 256 + binn * 4);
    };

    auto sts_stage = [&](int s) {
        float* aS = Asm + s * A_STAGE_FLT;
        float* bS = Bsm + s * B_STAGE_FLT;
        #pragma unroll
        for (int r = 0; r < 4; r++) {
            uint4 u = make_uint4(f2tf(pa[r].x), f2tf(pa[r].y), f2tf(pa[r].z), f2tf(pa[r].w));
            *(uint4*)(aS + (arow0 + r * 32) * A_STRIDE + ac16 * 4) = u;
        }
        #pragma unroll
        for (int r = 0; r < 4; r++) {
            uint32_t* bo = (uint32_t*)(bS + (boct0 + r * 4) * B_OCT_FLT) + bkk;
            bo[(bc0 + 0) * A_STRIDE] = f2tf(pb[r].x);
            bo[(bc0 + 1) * A_STRIDE] = f2tf(pb[r].y);
            bo[(bc0 + 2) * A_STRIDE] = f2tf(pb[r].z);
            bo[(bc0 + 3) * A_STRIDE] = f2tf(pb[r].w);
        }
    };

    // ---- per-thread ldmatrix lane address components ----
    const int aLaneRow = (l & 7) + ((l >> 3) & 1) * 8;   // row within 16-row tile
    const int aLaneCol = ((l >> 4) & 1) * 4;             // k quadrant select
    const uint32_t aOff0 = (uint32_t)((wm + aLaneRow) * A_STRIDE + aLaneCol) * 4;
    const uint32_t aOff1 = aOff0 + 16 * A_STRIDE * 4;

    const int bLaneOct = (l >> 4) & 1;                   // oct pair select
    const int bLaneK   = ((l >> 3) & 1) * 4;             // k quadrant select
    const uint32_t bOffBase =
        (uint32_t)((wnOct + bLaneOct) * B_OCT_FLT + (l & 7) * A_STRIDE + bLaneK) * 4;

    // ---- accumulators ----
    float acc[2][8][4];
    #pragma unroll
    for (int mi = 0; mi < 2; mi++)
        #pragma unroll
        for (int j = 0; j < 8; j++)
            #pragma unroll
            for (int q = 0; q < 4; q++) acc[mi][j][q] = 0.0f;

    // ---- prologue ----
    ldg_stage(0);
    sts_stage(0);
    ldg_stage(1);
    __syncthreads();

    for (int kt = 0; kt < NK; kt++) {
        const int s = kt & 1;
        const uint32_t sAst = sAu + (uint32_t)s * (A_STAGE_FLT * 4);
        const uint32_t sBst = sBu + (uint32_t)s * (B_STAGE_FLT * 4);

        #pragma unroll
        for (int ks = 0; ks < 4; ks++) {
            const uint32_t k4 = (uint32_t)(ks * 8) * 4;
            uint32_t aF[2][4], bF[8][2];
            ldm4(aF[0], sAst + aOff0 + k4);
            ldm4(aF[1], sAst + aOff1 + k4);
            #pragma unroll
            for (int p = 0; p < 4; p++)
                ldm4(&bF[2 * p][0], sBst + bOffBase + (uint32_t)(2 * p) * (B_OCT_FLT * 4) + k4);
            #pragma unroll
            for (int mi = 0; mi < 2; mi++)
                #pragma unroll
                for (int j = 0; j < 8; j++)
                    mma8(acc[mi][j], aF[mi], bF[j]);
        }

        if (kt + 1 < NK) {
            __syncthreads();              // all warps done reading buf[(kt+1)&1]
            sts_stage((kt + 1) & 1);      // regs hold kt+1
            if (kt + 2 < NK) ldg_stage(kt + 2);
            __syncthreads();              // stores visible
        }
    }

    // ---- epilogue: bias add + store ----
    const int r0 = bm + wm + lr;
    #pragma unroll
    for (int mi = 0; mi < 2; mi++) {
        #pragma unroll
        for (int j = 0; j < 8; j++) {
            const int n0 = bn + wn + j * 8 + lc * 2;
            const float b0v = Bias[n0];
            const float b1v = Bias[n0 + 1];
            float2 v0 = make_float2(acc[mi][j][0] + b0v, acc[mi][j][1] + b1v);
            float2 v1 = make_float2(acc[mi][j][2] + b0v, acc[mi][j][3] + b1v);
            *(float2*)(Y + (size_t)(r0 + mi * 16) * N_DIM + n0) = v0;
            *(float2*)(Y + (size_t)(r0 + mi * 16 + 8) * N_DIM + n0) = v1;
        }
    }
}

extern "C" void kernel_launch(void* const* d_in, const int* in_sizes, int n_in,
                              void* d_out, int out_size)
{
    const float* x    = (const float*)d_in[0];  // [512, 4096]
    const float* wt   = (const float*)d_in[1];  // [512, 512, 8, 8]
    const float* bias = (const float*)d_in[2];  // [512, 8]
    float* y          = (float*)d_out;          // [512, 4096]

    cudaFuncSetAttribute(oct_mma_tf32_ldm, cudaFuncAttributeMaxDynamicSharedMemorySize, SMEM_BYTES);
    dim3 grid(N_DIM / BN, M_DIM / BM);  // (32, 4) = 128 CTAs
    oct_mma_tf32_ldm<<<grid, THREADS, SMEM_BYTES>>>(x, wt, bias, y);
}

// round 9
// speedup vs baseline: 1.4025x; 1.4025x over previous
#include <cuda_runtime.h>
#include <cuda_fp16.h>
#include <cstdint>

// OctonionLinear as dense fp16 mma.sync GEMM, fp32 accumulate:
//   Y[b, n] = sum_kk X[b, kk] * Bop(n, kk) + bias[n]
//   Bop(n=8i+c, kk) = W[i*32768 + kk*8 + c]
// M=512, N=4096, K=4096.
// R9: m16n8k16 fp16 (same 10-bit mantissa as tf32 -> same accuracy) halves the
// HMMA instruction count, which R4/R6/R8 showed is the binding resource.

#define M_DIM 512
#define N_DIM 4096
#define K_DIM 4096
#define BM 128
#define BN 128
#define BK 32
#define NK (K_DIM / BK)            // 128
#define THREADS 256

#define A_STRIDE_H 40                         // fp16 per row (80 B, conflict-free)
#define A_STAGE_H (BM * A_STRIDE_H)           // 5120 halves = 10240 B
#define B_STAGE_H (BN * A_STRIDE_H)           // 5120 halves ([n=128][k=32+pad])
#define SMEM_BYTES ((2 * (A_STAGE_H + B_STAGE_H)) * 2)  // 40960 B

__device__ __forceinline__ uint32_t smem_u32(const void* p) {
    uint32_t a;
    asm("{ .reg .u64 t; cvta.to.shared.u64 t, %1; cvt.u32.u64 %0, t; }" : "=r"(a) : "l"(p));
    return a;
}
__device__ __forceinline__ uint32_t pk2(float a, float b) {
    __half2 h = __floats2half2_rn(a, b);
    return *(uint32_t*)&h;
}
__device__ __forceinline__ void ldm4(uint32_t* r, uint32_t addr) {
    asm volatile("ldmatrix.sync.aligned.m8n8.x4.shared.b16 {%0,%1,%2,%3}, [%4];"
                 : "=r"(r[0]), "=r"(r[1]), "=r"(r[2]), "=r"(r[3]) : "r"(addr));
}
__device__ __forceinline__ void mma16(float* c, const uint32_t* a, const uint32_t* b) {
    asm volatile(
        "mma.sync.aligned.m16n8k16.row.col.f32.f16.f16.f32 "
        "{%0,%1,%2,%3}, {%4,%5,%6,%7}, {%8,%9}, {%0,%1,%2,%3};"
        : "+f"(c[0]), "+f"(c[1]), "+f"(c[2]), "+f"(c[3])
        : "r"(a[0]), "r"(a[1]), "r"(a[2]), "r"(a[3]), "r"(b[0]), "r"(b[1]));
}

__global__ __launch_bounds__(THREADS)
void oct_mma_fp16(const float* __restrict__ X,
                  const float* __restrict__ W,
                  const float* __restrict__ Bias,
                  float* __restrict__ Y)
{
    extern __shared__ __half hsm[];
    __half* Asm = hsm;                         // 2 stages of A_STAGE_H
    __half* Bsm = hsm + 2 * A_STAGE_H;         // 2 stages of B_STAGE_H
    const uint32_t sAu = smem_u32(Asm);
    const uint32_t sBu = smem_u32(Bsm);

    const int t = threadIdx.x;
    const int w = t >> 5;
    const int l = t & 31;
    const int bm = blockIdx.y * BM;
    const int bn = blockIdx.x * BN;
    const int wm = (w & 3) * 32;          // warp M base
    const int wn = (w >> 2) * 64;         // warp N base
    const int wnOct = wn >> 3;            // 0 or 8

    const int lr = l >> 2;
    const int lc = l & 3;
    const int i0 = bn >> 3;

    // ---- A LDG/STS mapping: 4 float4 granules per thread ----
    const int arow0 = t >> 3;             // +32 per r
    const int ac16  = t & 7;              // float4 index within 32-float A row

    // ---- B LDG/STS mapping: 2 slots per thread, 2 granules each (kk, kk+1) ----
    const int bs    = t & 31;             // slot within oct
    const int bkk0  = (bs >> 1) * 2;      // even kk
    const int bch   = bs & 1;             // c-half (c 0-3 or 4-7)
    const int boct0 = t >> 5;             // oct for r=0; +8 for r=1

    float4 pa[4], pb[4];

    auto ldg_stage = [&](int kt) {
        #pragma unroll
        for (int r = 0; r < 4; r++)
            pa[r] = *(const float4*)(X + (size_t)(bm + arow0 + r * 32) * K_DIM
                                       + (size_t)kt * BK + ac16 * 4);
        #pragma unroll
        for (int r = 0; r < 2; r++) {
            const float* wb = W + (size_t)(i0 + boct0 + r * 8) * 32768
                                + (size_t)kt * 256 + bkk0 * 8 + bch * 4;
            pb[2 * r]     = *(const float4*)(wb);
            pb[2 * r + 1] = *(const float4*)(wb + 8);   // kk0+1, same c-half
        }
    };

    auto sts_stage = [&](int s) {
        __half* aS = Asm + s * A_STAGE_H;
        __half* bS = Bsm + s * B_STAGE_H;
        #pragma unroll
        for (int r = 0; r < 4; r++) {
            uint2 v;
            v.x = pk2(pa[r].x, pa[r].y);
            v.y = pk2(pa[r].z, pa[r].w);
            *(uint2*)(aS + (arow0 + r * 32) * A_STRIDE_H + ac16 * 4) = v;
        }
        #pragma unroll
        for (int r = 0; r < 2; r++) {
            const float* lo = (const float*)&pb[2 * r];
            const float* hi = (const float*)&pb[2 * r + 1];
            const int nb = (boct0 + r * 8) * 8 + bch * 4;
            #pragma unroll
            for (int c = 0; c < 4; c++)
                *(uint32_t*)(bS + (nb + c) * A_STRIDE_H + bkk0) = pk2(lo[c], hi[c]);
        }
    };

    // ---- ldmatrix lane addresses (bytes from stage base) ----
    const int aRow = wm + (l & 7) + ((l >> 3) & 1) * 8;
    const uint32_t aOff0 = (uint32_t)(aRow * A_STRIDE_H + ((l >> 4) & 1) * 8) * 2;
    const uint32_t aOff1 = aOff0 + 16 * A_STRIDE_H * 2;

    const int bRow = (wnOct + ((l >> 4) & 1)) * 8 + (l & 7);
    const uint32_t bOff0 = (uint32_t)(bRow * A_STRIDE_H + ((l >> 3) & 1) * 8) * 2;

    float acc[2][8][4];
    #pragma unroll
    for (int mi = 0; mi < 2; mi++)
        #pragma unroll
        for (int j = 0; j < 8; j++)
            #pragma unroll
            for (int q = 0; q < 4; q++) acc[mi][j][q] = 0.0f;

    // ---- prologue ----
    ldg_stage(0);
    sts_stage(0);
    ldg_stage(1);
    __syncthreads();

    for (int kt = 0; kt < NK; kt++) {
        const int s = kt & 1;
        const uint32_t sAst = sAu + (uint32_t)s * (A_STAGE_H * 2);
        const uint32_t sBst = sBu + (uint32_t)s * (B_STAGE_H * 2);

        #pragma unroll
        for (int kc = 0; kc < 2; kc++) {           // two k16 chunks per BK=32
            const uint32_t kb = (uint32_t)kc * 32; // 16 fp16 = 32 B
            uint32_t aF[2][4], bF[8][2];
            ldm4(aF[0], sAst + aOff0 + kb);
            ldm4(aF[1], sAst + aOff1 + kb);
            #pragma unroll
            for (int p = 0; p < 4; p++)
                ldm4(&bF[2 * p][0], sBst + bOff0 + (uint32_t)p * (16 * A_STRIDE_H * 2) + kb);
            #pragma unroll
            for (int mi = 0; mi < 2; mi++)
                #pragma unroll
                for (int j = 0; j < 8; j++)
                    mma16(acc[mi][j], aF[mi], bF[j]);
        }

        if (kt + 1 < NK) {
            __syncthreads();              // all warps done reading buf[(kt+1)&1]
            sts_stage((kt + 1) & 1);      // regs hold kt+1
            if (kt + 2 < NK) ldg_stage(kt + 2);
            __syncthreads();              // stores visible
        }
    }

    // ---- epilogue: bias add + store ----
    const int r0 = bm + wm + lr;
    #pragma unroll
    for (int mi = 0; mi < 2; mi++) {
        #pragma unroll
        for (int j = 0; j < 8; j++) {
            const int n0 = bn + wn + j * 8 + lc * 2;
            const float b0v = Bias[n0];
            const float b1v = Bias[n0 + 1];
            float2 v0 = make_float2(acc[mi][j][0] + b0v, acc[mi][j][1] + b1v);
            float2 v1 = make_float2(acc[mi][j][2] + b0v, acc[mi][j][3] + b1v);
            *(float2*)(Y + (size_t)(r0 + mi * 16) * N_DIM + n0) = v0;
            *(float2*)(Y + (size_t)(r0 + mi * 16 + 8) * N_DIM + n0) = v1;
        }
    }
}

extern "C" void kernel_launch(void* const* d_in, const int* in_sizes, int n_in,
                              void* d_out, int out_size)
{
    const float* x    = (const float*)d_in[0];  // [512, 4096]
    const float* wt   = (const float*)d_in[1];  // [512, 512, 8, 8]
    const float* bias = (const float*)d_in[2];  // [512, 8]
    float* y          = (float*)d_out;          // [512, 4096]

    cudaFuncSetAttribute(oct_mma_fp16, cudaFuncAttributeMaxDynamicSharedMemorySize, SMEM_BYTES);
    dim3 grid(N_DIM / BN, M_DIM / BM);  // (32, 4) = 128 CTAs
    oct_mma_fp16<<<grid, THREADS, SMEM_BYTES>>>(x, wt, bias, y);
}

// round 10
// speedup vs baseline: 1.6290x; 1.1615x over previous
#include <cuda_runtime.h>
#include <cuda_fp16.h>
#include <cstdint>

// OctonionLinear as dense fp16 mma.sync GEMM, fp32 accumulate:
//   Y[b, n] = sum_kk X[b, kk] * Bop(n, kk) + bias[n]
//   Bop(n=8i+c, kk) = W[i*32768 + kk*8 + c]
// M=512, N=4096, K=4096.
// R10: 3-stage reg->STS pipeline (ONE __syncthreads per kt) + split-K(2)
// -> 256 CTAs, 2 co-resident per SM (4 warps/SMSP), atomicAdd epilogue.

#define M_DIM 512
#define N_DIM 4096
#define K_DIM 4096
#define BM 128
#define BN 128
#define BK 32
#define NK (K_DIM / BK)            // 128
#define KSPLIT 2
#define NK_PER (NK / KSPLIT)       // 64
#define THREADS 256
#define STAGES 3

#define A_STRIDE_H 40                         // fp16 per row (80 B, conflict-free)
#define A_STAGE_H (BM * A_STRIDE_H)           // 5120 halves = 10240 B
#define B_STAGE_H (BN * A_STRIDE_H)           // 5120 halves ([n=128][k=32+pad])
#define SMEM_BYTES ((STAGES * (A_STAGE_H + B_STAGE_H)) * 2)  // 61440 B

__device__ __forceinline__ uint32_t smem_u32(const void* p) {
    uint32_t a;
    asm("{ .reg .u64 t; cvta.to.shared.u64 t, %1; cvt.u32.u64 %0, t; }" : "=r"(a) : "l"(p));
    return a;
}
__device__ __forceinline__ uint32_t pk2(float a, float b) {
    __half2 h = __floats2half2_rn(a, b);
    return *(uint32_t*)&h;
}
__device__ __forceinline__ void ldm4(uint32_t* r, uint32_t addr) {
    asm volatile("ldmatrix.sync.aligned.m8n8.x4.shared.b16 {%0,%1,%2,%3}, [%4];"
                 : "=r"(r[0]), "=r"(r[1]), "=r"(r[2]), "=r"(r[3]) : "r"(addr));
}
__device__ __forceinline__ void mma16(float* c, const uint32_t* a, const uint32_t* b) {
    asm volatile(
        "mma.sync.aligned.m16n8k16.row.col.f32.f16.f16.f32 "
        "{%0,%1,%2,%3}, {%4,%5,%6,%7}, {%8,%9}, {%0,%1,%2,%3};"
        : "+f"(c[0]), "+f"(c[1]), "+f"(c[2]), "+f"(c[3])
        : "r"(a[0]), "r"(a[1]), "r"(a[2]), "r"(a[3]), "r"(b[0]), "r"(b[1]));
}

__global__ __launch_bounds__(THREADS, 2)
void oct_mma_fp16_sk(const float* __restrict__ X,
                     const float* __restrict__ W,
                     const float* __restrict__ Bias,
                     float* __restrict__ Y)
{
    extern __shared__ __half hsm[];
    __half* Asm = hsm;                             // STAGES of A_STAGE_H
    __half* Bsm = hsm + STAGES * A_STAGE_H;        // STAGES of B_STAGE_H
    const uint32_t sAu = smem_u32(Asm);
    const uint32_t sBu = smem_u32(Bsm);

    const int t = threadIdx.x;
    const int w = t >> 5;
    const int l = t & 31;
    const int bm = blockIdx.y * BM;
    const int bn = blockIdx.x * BN;
    const int ks0 = blockIdx.z * NK_PER;
    const int wm = (w & 3) * 32;          // warp M base
    const int wn = (w >> 2) * 64;         // warp N base
    const int wnOct = wn >> 3;            // 0 or 8

    const int lr = l >> 2;
    const int lc = l & 3;
    const int i0 = bn >> 3;

    // ---- A LDG/STS mapping: 4 float4 granules per thread ----
    const int arow0 = t >> 3;             // +32 per r
    const int ac16  = t & 7;              // float4 index within 32-float A row

    // ---- B LDG/STS mapping: 2 slots per thread, 2 granules each (kk, kk+1) ----
    const int bs    = t & 31;             // slot within oct
    const int bkk0  = (bs >> 1) * 2;      // even kk
    const int bch   = bs & 1;             // c-half (c 0-3 or 4-7)
    const int boct0 = t >> 5;             // oct for r=0; +8 for r=1

    float4 pa[4], pb[4];

    auto ldg_stage = [&](int kt) {
        #pragma unroll
        for (int r = 0; r < 4; r++)
            pa[r] = *(const float4*)(X + (size_t)(bm + arow0 + r * 32) * K_DIM
                                       + (size_t)kt * BK + ac16 * 4);
        #pragma unroll
        for (int r = 0; r < 2; r++) {
            const float* wb = W + (size_t)(i0 + boct0 + r * 8) * 32768
                                + (size_t)kt * 256 + bkk0 * 8 + bch * 4;
            pb[2 * r]     = *(const float4*)(wb);
            pb[2 * r + 1] = *(const float4*)(wb + 8);   // kk0+1, same c-half
        }
    };

    auto sts_stage = [&](int s) {
        __half* aS = Asm + s * A_STAGE_H;
        __half* bS = Bsm + s * B_STAGE_H;
        #pragma unroll
        for (int r = 0; r < 4; r++) {
            uint2 v;
            v.x = pk2(pa[r].x, pa[r].y);
            v.y = pk2(pa[r].z, pa[r].w);
            *(uint2*)(aS + (arow0 + r * 32) * A_STRIDE_H + ac16 * 4) = v;
        }
        #pragma unroll
        for (int r = 0; r < 2; r++) {
            const float* lo = (const float*)&pb[2 * r];
            const float* hi = (const float*)&pb[2 * r + 1];
            const int nb = (boct0 + r * 8) * 8 + bch * 4;
            #pragma unroll
            for (int c = 0; c < 4; c++)
                *(uint32_t*)(bS + (nb + c) * A_STRIDE_H + bkk0) = pk2(lo[c], hi[c]);
        }
    };

    // ---- ldmatrix lane addresses (bytes from stage base) ----
    const int aRow = wm + (l & 7) + ((l >> 3) & 1) * 8;
    const uint32_t aOff0 = (uint32_t)(aRow * A_STRIDE_H + ((l >> 4) & 1) * 8) * 2;
    const uint32_t aOff1 = aOff0 + 16 * A_STRIDE_H * 2;

    const int bRow = (wnOct + ((l >> 4) & 1)) * 8 + (l & 7);
    const uint32_t bOff0 = (uint32_t)(bRow * A_STRIDE_H + ((l >> 3) & 1) * 8) * 2;

    // ---- acc init: split 0 carries bias, split 1 zero ----
    float acc[2][8][4];
    if (blockIdx.z == 0) {
        #pragma unroll
        for (int j = 0; j < 8; j++) {
            const int n0 = bn + wn + j * 8 + lc * 2;
            const float b0v = Bias[n0];
            const float b1v = Bias[n0 + 1];
            #pragma unroll
            for (int mi = 0; mi < 2; mi++) {
                acc[mi][j][0] = b0v; acc[mi][j][1] = b1v;
                acc[mi][j][2] = b0v; acc[mi][j][3] = b1v;
            }
        }
    } else {
        #pragma unroll
        for (int mi = 0; mi < 2; mi++)
            #pragma unroll
            for (int j = 0; j < 8; j++)
                #pragma unroll
                for (int q = 0; q < 4; q++) acc[mi][j][q] = 0.0f;
    }

    // ---- prologue: fill stages 0,1; regs hold tile 2 ----
    ldg_stage(ks0 + 0);
    sts_stage(0);
    ldg_stage(ks0 + 1);
    sts_stage(1);
    ldg_stage(ks0 + 2);
    __syncthreads();

    for (int kt = 0; kt < NK_PER; kt++) {
        const int s = kt % STAGES;
        const uint32_t sAst = sAu + (uint32_t)s * (A_STAGE_H * 2);
        const uint32_t sBst = sBu + (uint32_t)s * (B_STAGE_H * 2);

        #pragma unroll
        for (int kc = 0; kc < 2; kc++) {           // two k16 chunks per BK=32
            const uint32_t kb = (uint32_t)kc * 32; // 16 fp16 = 32 B
            uint32_t aF[2][4], bF[8][2];
            ldm4(aF[0], sAst + aOff0 + kb);
            ldm4(aF[1], sAst + aOff1 + kb);
            #pragma unroll
            for (int p = 0; p < 4; p++)
                ldm4(&bF[2 * p][0], sBst + bOff0 + (uint32_t)p * (16 * A_STRIDE_H * 2) + kb);
            #pragma unroll
            for (int mi = 0; mi < 2; mi++)
                #pragma unroll
                for (int j = 0; j < 8; j++)
                    mma16(acc[mi][j], aF[mi], bF[j]);
        }

        // store tile kt+2 (in regs) into buf (kt+2)%3; last read 2 barriers ago
        if (kt + 2 < NK_PER) {
            sts_stage((kt + 2) % STAGES);
            if (kt + 3 < NK_PER) ldg_stage(ks0 + kt + 3);
        }
        if (kt + 1 < NK_PER) __syncthreads();
    }

    // ---- epilogue: atomicAdd partial sums into zeroed Y ----
    const int r0 = bm + wm + lr;
    #pragma unroll
    for (int mi = 0; mi < 2; mi++) {
        #pragma unroll
        for (int j = 0; j < 8; j++) {
            const int n0 = bn + wn + j * 8 + lc * 2;
            float* y0 = Y + (size_t)(r0 + mi * 16) * N_DIM + n0;
            float* y1 = Y + (size_t)(r0 + mi * 16 + 8) * N_DIM + n0;
            atomicAdd(y0,     acc[mi][j][0]);
            atomicAdd(y0 + 1, acc[mi][j][1]);
            atomicAdd(y1,     acc[mi][j][2]);
            atomicAdd(y1 + 1, acc[mi][j][3]);
        }
    }
}

extern "C" void kernel_launch(void* const* d_in, const int* in_sizes, int n_in,
                              void* d_out, int out_size)
{
    const float* x    = (const float*)d_in[0];  // [512, 4096]
    const float* wt   = (const float*)d_in[1];  // [512, 512, 8, 8]
    const float* bias = (const float*)d_in[2];  // [512, 8]
    float* y          = (float*)d_out;          // [512, 4096]

    cudaMemsetAsync(y, 0, (size_t)M_DIM * N_DIM * sizeof(float));

    cudaFuncSetAttribute(oct_mma_fp16_sk, cudaFuncAttributeMaxDynamicSharedMemorySize, SMEM_BYTES);
    dim3 grid(N_DIM / BN, M_DIM / BM, KSPLIT);  // (32, 4, 2) = 256 CTAs
    oct_mma_fp16_sk<<<grid, THREADS, SMEM_BYTES>>>(x, wt, bias, y);
}

// round 11
// speedup vs baseline: 1.6762x; 1.0290x over previous
#include <cuda_runtime.h>
#include <cuda_fp16.h>
#include <cstdint>

// OctonionLinear as dense fp16 mma.sync GEMM, fp32 accumulate.
//   Y[b, n] = sum_kk X[b, kk] * Bop(n, kk) + bias[n]
//   Bop(n=8i+c, kk) = W[i*32768 + kk*8 + c]
// R11: pre-convert X,W -> fp16 device globals (Wh laid out [n][kk] = B operand),
// GEMM loads tiles with cp.async.cg (L2->smem, L1 bypass, no CVT/STS/staging),
// 4-stage pipeline, split-K(2), 2 CTAs/SM, atomicAdd epilogue.

#define M_DIM 512
#define N_DIM 4096
#define K_DIM 4096
#define BM 128
#define BN 128
#define BK 32
#define NK (K_DIM / BK)            // 128
#define KSPLIT 2
#define NK_PER (NK / KSPLIT)       // 64
#define THREADS 256
#define STAGES 4

#define A_STRIDE_H 40                          // fp16 per row (80 B, 16B-mult, conflict-free)
#define TILE_H (BM * A_STRIDE_H)               // 5120 halves = 10240 B per operand tile
#define SMEM_BYTES (STAGES * 2 * TILE_H * 2)   // 81920 B

__device__ __align__(16) __half Wh_g[(size_t)N_DIM * K_DIM];  // 32 MB, [n][kk]
__device__ __align__(16) __half Xh_g[(size_t)M_DIM * K_DIM];  // 4 MB,  [b][kk]

// ---------------- conversion kernel ----------------
#define CONV_WBLOCKS 8192   // 512 octets x 16 kk-chunks of 256
#define CONV_XBLOCKS 2048   // 2M floats / 1024 per block

__global__ __launch_bounds__(256)
void oct_convert(const float* __restrict__ W, const float* __restrict__ X)
{
    const int t = threadIdx.x;
    const int b = blockIdx.x;
    if (b < CONV_WBLOCKS) {
        const int i = b >> 4;
        const int kk0 = (b & 15) << 8;
        __shared__ __half sm[8][264];          // [c][kk] ; 528B row stride (16B mult)
        const float4* src = (const float4*)(W + (size_t)i * 32768 + (size_t)kk0 * 8);
        #pragma unroll
        for (int r = 0; r < 2; r++) {
            const int g = t + r * 256;         // float4 id: kk = g>>1, c0 = (g&1)*4
            float4 v = src[g];
            const int kk = g >> 1, c0 = (g & 1) * 4;
            sm[c0 + 0][kk] = __float2half_rn(v.x);
            sm[c0 + 1][kk] = __float2half_rn(v.y);
            sm[c0 + 2][kk] = __float2half_rn(v.z);
            sm[c0 + 3][kk] = __float2half_rn(v.w);
        }
        __syncthreads();
        const int c = t >> 5, j0 = (t & 31) * 8;
        uint4 out = *(const uint4*)&sm[c][j0];
        *(uint4*)(Wh_g + (size_t)(8 * i + c) * K_DIM + kk0 + j0) = out;
    } else {
        const size_t gid = (size_t)(b - CONV_WBLOCKS) * 1024 + (size_t)t * 4;
        float4 v = *(const float4*)(X + gid);
        __half2* dst = (__half2*)(Xh_g + gid);
        dst[0] = __floats2half2_rn(v.x, v.y);
        dst[1] = __floats2half2_rn(v.z, v.w);
    }
}

// ---------------- GEMM kernel ----------------
__device__ __forceinline__ uint32_t smem_u32(const void* p) {
    uint32_t a;
    asm("{ .reg .u64 t; cvta.to.shared.u64 t, %1; cvt.u32.u64 %0, t; }" : "=r"(a) : "l"(p));
    return a;
}
__device__ __forceinline__ void cp16(uint32_t dst, const void* src) {
    asm volatile("cp.async.cg.shared.global [%0], [%1], 16;" :: "r"(dst), "l"(src));
}
#define CP_COMMIT() asm volatile("cp.async.commit_group;" ::: "memory")
#define CP_WAIT2()  asm volatile("cp.async.wait_group 2;" ::: "memory")
__device__ __forceinline__ void ldm4(uint32_t* r, uint32_t addr) {
    asm volatile("ldmatrix.sync.aligned.m8n8.x4.shared.b16 {%0,%1,%2,%3}, [%4];"
                 : "=r"(r[0]), "=r"(r[1]), "=r"(r[2]), "=r"(r[3]) : "r"(addr));
}
__device__ __forceinline__ void mma16(float* c, const uint32_t* a, const uint32_t* b) {
    asm volatile(
        "mma.sync.aligned.m16n8k16.row.col.f32.f16.f16.f32 "
        "{%0,%1,%2,%3}, {%4,%5,%6,%7}, {%8,%9}, {%0,%1,%2,%3};"
        : "+f"(c[0]), "+f"(c[1]), "+f"(c[2]), "+f"(c[3])
        : "r"(a[0]), "r"(a[1]), "r"(a[2]), "r"(a[3]), "r"(b[0]), "r"(b[1]));
}

__global__ __launch_bounds__(THREADS, 2)
void oct_mma_fp16_cp(const float* __restrict__ Bias, float* __restrict__ Y)
{
    extern __shared__ __half hsm[];
    __half* Asm = hsm;                         // STAGES tiles of TILE_H
    __half* Bsm = hsm + STAGES * TILE_H;
    const uint32_t sAu = smem_u32(Asm);
    const uint32_t sBu = smem_u32(Bsm);

    const int t = threadIdx.x;
    const int w = t >> 5;
    const int l = t & 31;
    const int bm = blockIdx.y * BM;
    const int bn = blockIdx.x * BN;
    const int ks0 = blockIdx.z * NK_PER;
    const int wm = (w & 3) * 32;
    const int wn = (w >> 2) * 64;
    const int wnOct = wn >> 3;

    const int lr = l >> 2;
    const int lc = l & 3;

    // ---- cp.async mapping: per thread 2 A + 2 B granules of 16B ----
    const int grow0 = t >> 2;              // +64 per r
    const int gc16  = t & 3;               // 16B column within 64B row

    auto issue_cp = [&](int kt, int s) {
        const uint32_t aBase = sAu + (uint32_t)s * (TILE_H * 2);
        const uint32_t bBase = sBu + (uint32_t)s * (TILE_H * 2);
        const size_t kc0 = (size_t)kt * BK + gc16 * 8;
        #pragma unroll
        for (int r = 0; r < 2; r++) {
            const int row = grow0 + r * 64;
            cp16(aBase + (uint32_t)row * 80 + (uint32_t)gc16 * 16,
                 Xh_g + (size_t)(bm + row) * K_DIM + kc0);
        }
        #pragma unroll
        for (int r = 0; r < 2; r++) {
            const int row = grow0 + r * 64;
            cp16(bBase + (uint32_t)row * 80 + (uint32_t)gc16 * 16,
                 Wh_g + (size_t)(bn + row) * K_DIM + kc0);
        }
    };

    // ---- ldmatrix lane addresses (bytes from stage base) ----
    const int aRow = wm + (l & 7) + ((l >> 3) & 1) * 8;
    const uint32_t aOff0 = (uint32_t)(aRow * A_STRIDE_H + ((l >> 4) & 1) * 8) * 2;
    const uint32_t aOff1 = aOff0 + 16 * A_STRIDE_H * 2;
    const int bRow = (wnOct + ((l >> 4) & 1)) * 8 + (l & 7);
    const uint32_t bOff0 = (uint32_t)(bRow * A_STRIDE_H + ((l >> 3) & 1) * 8) * 2;

    // ---- acc init: split 0 carries bias, split 1 zero ----
    float acc[2][8][4];
    if (blockIdx.z == 0) {
        #pragma unroll
        for (int j = 0; j < 8; j++) {
            const int n0 = bn + wn + j * 8 + lc * 2;
            const float b0v = Bias[n0];
            const float b1v = Bias[n0 + 1];
            #pragma unroll
            for (int mi = 0; mi < 2; mi++) {
                acc[mi][j][0] = b0v; acc[mi][j][1] = b1v;
                acc[mi][j][2] = b0v; acc[mi][j][3] = b1v;
            }
        }
    } else {
        #pragma unroll
        for (int mi = 0; mi < 2; mi++)
            #pragma unroll
            for (int j = 0; j < 8; j++)
                #pragma unroll
                for (int q = 0; q < 4; q++) acc[mi][j][q] = 0.0f;
    }

    // ---- prologue: stages 0..2 in flight ----
    #pragma unroll
    for (int s = 0; s < STAGES - 1; s++) {
        issue_cp(ks0 + s, s);
        CP_COMMIT();
    }
    CP_WAIT2();            // stage 0 complete
    __syncthreads();

    for (int kt = 0; kt < NK_PER; kt++) {
        const int s = kt & (STAGES - 1);
        const uint32_t sAst = sAu + (uint32_t)s * (TILE_H * 2);
        const uint32_t sBst = sBu + (uint32_t)s * (TILE_H * 2);

        // refill slot (kt+3)&3 (== slot read in iter kt-1, barrier-protected)
        if (kt + STAGES - 1 < NK_PER)
            issue_cp(ks0 + kt + STAGES - 1, (kt + STAGES - 1) & (STAGES - 1));
        CP_COMMIT();

        #pragma unroll
        for (int kc = 0; kc < 2; kc++) {
            const uint32_t kb = (uint32_t)kc * 32;   // 16 fp16 = 32 B
            uint32_t aF[2][4], bF[8][2];
            ldm4(aF[0], sAst + aOff0 + kb);
            ldm4(aF[1], sAst + aOff1 + kb);
            #pragma unroll
            for (int p = 0; p < 4; p++)
                ldm4(&bF[2 * p][0], sBst + bOff0 + (uint32_t)p * (16 * A_STRIDE_H * 2) + kb);
            #pragma unroll
            for (int mi = 0; mi < 2; mi++)
                #pragma unroll
                for (int j = 0; j < 8; j++)
                    mma16(acc[mi][j], aF[mi], bF[j]);
        }

        if (kt + 1 < NK_PER) {
            CP_WAIT2();           // stage kt+1 complete
            __syncthreads();      // and slot (kt)&3 free for refill next iter
        }
    }

    // ---- epilogue: atomicAdd partial sums into zeroed Y ----
    const int r0 = bm + wm + lr;
    #pragma unroll
    for (int mi = 0; mi < 2; mi++) {
        #pragma unroll
        for (int j = 0; j < 8; j++) {
            const int n0 = bn + wn + j * 8 + lc * 2;
            float* y0 = Y + (size_t)(r0 + mi * 16) * N_DIM + n0;
            float* y1 = Y + (size_t)(r0 + mi * 16 + 8) * N_DIM + n0;
            atomicAdd(y0,     acc[mi][j][0]);
            atomicAdd(y0 + 1, acc[mi][j][1]);
            atomicAdd(y1,     acc[mi][j][2]);
            atomicAdd(y1 + 1, acc[mi][j][3]);
        }
    }
}

extern "C" void kernel_launch(void* const* d_in, const int* in_sizes, int n_in,
                              void* d_out, int out_size)
{
    const float* x    = (const float*)d_in[0];  // [512, 4096]
    const float* wt   = (const float*)d_in[1];  // [512, 512, 8, 8]
    const float* bias = (const float*)d_in[2];  // [512, 8]
    float* y          = (float*)d_out;          // [512, 4096]

    oct_convert<<<CONV_WBLOCKS + CONV_XBLOCKS, 256>>>(wt, x);
    cudaMemsetAsync(y, 0, (size_t)M_DIM * N_DIM * sizeof(float));

    cudaFuncSetAttribute(oct_mma_fp16_cp, cudaFuncAttributeMaxDynamicSharedMemorySize, SMEM_BYTES);
    dim3 grid(N_DIM / BN, M_DIM / BM, KSPLIT);  // (32, 4, 2) = 256 CTAs
    oct_mma_fp16_cp<<<grid, THREADS, SMEM_BYTES>>>(bias, y);
}